// round 3
// baseline (speedup 1.0000x reference)
#include <cuda_runtime.h>

// Problem constants (fixed shapes from reference)
#define BB 4
#define NN 19
#define HH 512
#define WW 512
#define HWc (HH * WW)          // 262144
#define CC 57
#define PAIRS (BB * NN)        // 76
#define TILES 32
#define NBLOCKS (PAIRS * TILES)             // 2432
#define THREADS 256
#define V_PER_TILE (HWc / 4 / TILES)        // 2048 float4 per tile
#define V_PER_THREAD (V_PER_TILE / THREADS) // 8 float4 per thread per plane

// Per-CTA partials: every slot written each launch -> no zero kernel needed.
__device__ float g_pbce[NBLOCKS];
__device__ float g_pl1x[NBLOCKS];
__device__ float g_pl1y[NBLOCKS];
__device__ float g_pcnt[NBLOCKS];
__device__ unsigned int g_count = 0;   // last-block-done counter; reset by last block

__global__ __launch_bounds__(THREADS) void hm_main_kernel(
    const float* __restrict__ fm, const float* __restrict__ lms,
    float* __restrict__ out)
{
    const int pair = blockIdx.x / TILES;
    const int tile = blockIdx.x % TILES;
    const int b = pair / NN;
    const int n = pair % NN;

    // landmark -> integer center (matches (lm * [H,W]).astype(int32) truncation)
    const float lx = lms[pair * 2 + 0];
    const float ly = lms[pair * 2 + 1];
    const int x = (int)(lx * (float)HH);
    const int y = (int)(ly * (float)WW);

    const size_t base = ((size_t)(b * CC + n)) * (size_t)HWc;
    const float4* __restrict__ pL = (const float4*)(fm + base);
    const float4* __restrict__ pX = (const float4*)(fm + base + (size_t)NN * HWc);
    const float4* __restrict__ pY = (const float4*)(fm + base + (size_t)(2 * NN) * HWc);

    float bce = 0.0f, l1x = 0.0f, l1y = 0.0f;
    int cnt = 0;

    const int vbase = tile * V_PER_TILE + threadIdx.x;

    #pragma unroll
    for (int k = 0; k < V_PER_THREAD; k++) {
        const int v = vbase + k * THREADS;
        const float4 L  = __ldcs(pL + v);   // evict-streaming: 239MB, no reuse
        const float4 PX = __ldcs(pX + v);
        const float4 PY = __ldcs(pY + v);

        const int h = v >> 7;           // v / 128 (128 float4 per row)
        const int w = (v & 127) << 2;   // starting column of this float4

        const int di = h - x;           // row delta (constant across the 4 lanes)
        const int di2 = di * di;
        const float offx = -(float)di * (1.0f / 40.0f);

        float Lv[4]  = {L.x, L.y, L.z, L.w};
        float PXv[4] = {PX.x, PX.y, PX.z, PX.w};
        float PYv[4] = {PY.x, PY.y, PY.z, PY.w};

        #pragma unroll
        for (int j = 0; j < 4; j++) {
            const int dj = (w + j) - y;
            const bool heat = (di2 + dj * dj) <= 1600;   // == (sqrt(d2) <= 40)
            const float l = Lv[j];
            // softplus(-|l|) via fast MUFU log/exp (rel_err budget 1e-3; this is ~1e-6)
            const float sp = __logf(1.0f + __expf(-fabsf(l)));
            bce += fmaxf(l, 0.0f) + sp - (heat ? l : 0.0f);
            if (heat) {
                const float offy = -(float)dj * (1.0f / 40.0f);
                l1x += fabsf(PXv[j] - offx);
                l1y += fabsf(PYv[j] - offy);
                cnt++;
            }
        }
    }

    // block reduction: warp shfl, then cross-warp via smem, then per-CTA store
    float c = (float)cnt;
    #pragma unroll
    for (int o = 16; o > 0; o >>= 1) {
        bce += __shfl_down_sync(0xFFFFFFFFu, bce, o);
        l1x += __shfl_down_sync(0xFFFFFFFFu, l1x, o);
        l1y += __shfl_down_sync(0xFFFFFFFFu, l1y, o);
        c   += __shfl_down_sync(0xFFFFFFFFu, c, o);
    }

    __shared__ float s0[8], s1[8], s2[8], s3[8];
    const int warp = threadIdx.x >> 5;
    const int lane = threadIdx.x & 31;
    if (lane == 0) { s0[warp] = bce; s1[warp] = l1x; s2[warp] = l1y; s3[warp] = c; }
    __syncthreads();

    if (warp == 0) {
        float v0 = (lane < 8) ? s0[lane] : 0.0f;
        float v1 = (lane < 8) ? s1[lane] : 0.0f;
        float v2 = (lane < 8) ? s2[lane] : 0.0f;
        float v3 = (lane < 8) ? s3[lane] : 0.0f;
        #pragma unroll
        for (int o = 4; o > 0; o >>= 1) {
            v0 += __shfl_down_sync(0xFFFFFFFFu, v0, o);
            v1 += __shfl_down_sync(0xFFFFFFFFu, v1, o);
            v2 += __shfl_down_sync(0xFFFFFFFFu, v2, o);
            v3 += __shfl_down_sync(0xFFFFFFFFu, v3, o);
        }
        if (lane == 0) {
            g_pbce[blockIdx.x] = v0;
            g_pl1x[blockIdx.x] = v1;
            g_pl1y[blockIdx.x] = v2;
            g_pcnt[blockIdx.x] = v3;
        }
    }

    // ---- last-block-done: fused finalize ----
    __shared__ bool s_last;
    __threadfence();                       // release: partials visible before count
    if (threadIdx.x == 0) {
        unsigned int t = atomicAdd(&g_count, 1u);
        s_last = (t == (unsigned int)(NBLOCKS - 1));
    }
    __syncthreads();
    if (!s_last) return;

    __threadfence();                       // acquire side
    if (threadIdx.x == 0) g_count = 0;     // reset for next graph replay

    // 8 warps: warp w handles pairs w, w+8, ...; lane indexes the 32 tiles.
    float acc = 0.0f;
    for (int p = warp; p < PAIRS; p += 8) {
        const int idx = p * TILES + lane;  // TILES == 32 == warp width
        float vb = g_pbce[idx];
        float vx = g_pl1x[idx];
        float vy = g_pl1y[idx];
        float vc = g_pcnt[idx];
        #pragma unroll
        for (int o = 16; o > 0; o >>= 1) {
            vb += __shfl_down_sync(0xFFFFFFFFu, vb, o);
            vx += __shfl_down_sync(0xFFFFFFFFu, vx, o);
            vy += __shfl_down_sync(0xFFFFFFFFu, vy, o);
            vc += __shfl_down_sync(0xFFFFFFFFu, vc, o);
        }
        if (lane == 0)
            acc += 2.0f * vb * (1.0f / (float)HWc) + (vx + vy) / vc;
    }

    __shared__ float sacc[8];
    if (lane == 0) sacc[warp] = acc;
    __syncthreads();
    if (threadIdx.x == 0) {
        float sum = 0.0f;
        #pragma unroll
        for (int i = 0; i < 8; i++) sum += sacc[i];
        out[0] = sum / (float)PAIRS;
    }
}

extern "C" void kernel_launch(void* const* d_in, const int* in_sizes, int n_in,
                              void* d_out, int out_size)
{
    const float* fm  = (const float*)d_in[0];   // feature_maps (4,57,512,512) f32
    const float* lms = (const float*)d_in[1];   // landmarks (4,19,2) f32
    float* out = (float*)d_out;

    hm_main_kernel<<<NBLOCKS, THREADS>>>(fm, lms, out);
}

// round 4
// speedup vs baseline: 1.0316x; 1.0316x over previous
#include <cuda_runtime.h>

// Problem constants (fixed shapes from reference)
#define BB 4
#define NN 19
#define HH 512
#define WW 512
#define HWc (HH * WW)          // 262144
#define CC 57
#define PAIRS (BB * NN)        // 76
#define TILES 32
#define NBLOCKS (PAIRS * TILES)             // 2432
#define THREADS 256
#define V_PER_TILE (HWc / 4 / TILES)        // 2048 float4 per tile
#define V_PER_THREAD (V_PER_TILE / THREADS) // 8 float4 per thread per plane

// Per-CTA partials: every slot written each launch -> no zero kernel needed.
__device__ float g_pbce[NBLOCKS];
__device__ float g_pl1x[NBLOCKS];
__device__ float g_pl1y[NBLOCKS];
__device__ float g_pcnt[NBLOCKS];
__device__ unsigned int g_count = 0;   // last-block-done counter; reset by last block

__global__ __launch_bounds__(THREADS) void hm_main_kernel(
    const float* __restrict__ fm, const float* __restrict__ lms,
    float* __restrict__ out)
{
    const int pair = blockIdx.x / TILES;
    const int tile = blockIdx.x % TILES;
    const int b = pair / NN;
    const int n = pair % NN;

    // landmark -> integer center (matches (lm * [H,W]).astype(int32) truncation)
    const float lx = lms[pair * 2 + 0];
    const float ly = lms[pair * 2 + 1];
    const int x = (int)(lx * (float)HH);
    const int y = (int)(ly * (float)WW);

    const size_t base = ((size_t)(b * CC + n)) * (size_t)HWc;
    const float4* __restrict__ pL = (const float4*)(fm + base);
    const float4* __restrict__ pX = (const float4*)(fm + base + (size_t)NN * HWc);
    const float4* __restrict__ pY = (const float4*)(fm + base + (size_t)(2 * NN) * HWc);

    float bce = 0.0f, l1x = 0.0f, l1y = 0.0f;
    int cnt = 0;

    const int vbase = tile * V_PER_TILE + threadIdx.x;

    #pragma unroll
    for (int k = 0; k < V_PER_THREAD; k++) {
        const int v = vbase + k * THREADS;
        const float4 L  = __ldcs(pL + v);   // evict-streaming: 239MB, no reuse
        const float4 PX = __ldcs(pX + v);
        const float4 PY = __ldcs(pY + v);

        const int h = v >> 7;           // v / 128 (128 float4 per row)
        const int w = (v & 127) << 2;   // starting column of this float4

        const int di = h - x;           // row delta (constant across the 4 lanes)
        const int di2 = di * di;
        const float offx = -(float)di * (1.0f / 40.0f);

        float Lv[4]  = {L.x, L.y, L.z, L.w};
        float PXv[4] = {PX.x, PX.y, PX.z, PX.w};
        float PYv[4] = {PY.x, PY.y, PY.z, PY.w};

        #pragma unroll
        for (int j = 0; j < 4; j++) {
            const int dj = (w + j) - y;
            const bool heat = (di2 + dj * dj) <= 1600;   // == (sqrt(d2) <= 40)
            const float l = Lv[j];
            // softplus(-|l|) via fast MUFU log/exp (rel_err budget 1e-3; this is ~1e-6)
            const float sp = __logf(1.0f + __expf(-fabsf(l)));
            bce += fmaxf(l, 0.0f) + sp - (heat ? l : 0.0f);
            if (heat) {
                const float offy = -(float)dj * (1.0f / 40.0f);
                l1x += fabsf(PXv[j] - offx);
                l1y += fabsf(PYv[j] - offy);
                cnt++;
            }
        }
    }

    // block reduction: warp shfl, then cross-warp via smem, then per-CTA store
    float c = (float)cnt;
    #pragma unroll
    for (int o = 16; o > 0; o >>= 1) {
        bce += __shfl_down_sync(0xFFFFFFFFu, bce, o);
        l1x += __shfl_down_sync(0xFFFFFFFFu, l1x, o);
        l1y += __shfl_down_sync(0xFFFFFFFFu, l1y, o);
        c   += __shfl_down_sync(0xFFFFFFFFu, c, o);
    }

    __shared__ float s0[8], s1[8], s2[8], s3[8];
    const int warp = threadIdx.x >> 5;
    const int lane = threadIdx.x & 31;
    if (lane == 0) { s0[warp] = bce; s1[warp] = l1x; s2[warp] = l1y; s3[warp] = c; }
    __syncthreads();

    // ---- last-block-done: fused finalize (threadFenceReduction pattern) ----
    __shared__ bool s_last;
    if (threadIdx.x == 0) {
        float v0 = 0.f, v1 = 0.f, v2 = 0.f, v3 = 0.f;
        #pragma unroll
        for (int i = 0; i < 8; i++) {
            v0 += s0[i]; v1 += s1[i]; v2 += s2[i]; v3 += s3[i];
        }
        g_pbce[blockIdx.x] = v0;
        g_pl1x[blockIdx.x] = v1;
        g_pl1y[blockIdx.x] = v2;
        g_pcnt[blockIdx.x] = v3;
        __threadfence();   // release: this thread's partial stores before the count
        unsigned int t = atomicAdd(&g_count, 1u);
        s_last = (t == (unsigned int)(NBLOCKS - 1));
    }
    __syncthreads();
    if (!s_last) return;

    if (threadIdx.x == 0) g_count = 0;     // reset for next graph replay

    // 8 warps: warp w handles pairs w, w+8, ...; lane indexes the 32 tiles.
    float acc = 0.0f;
    for (int p = warp; p < PAIRS; p += 8) {
        const int idx = p * TILES + lane;  // TILES == 32 == warp width
        float vb = __ldcg(&g_pbce[idx]);   // L1-bypass: read other CTAs' stores
        float vx = __ldcg(&g_pl1x[idx]);
        float vy = __ldcg(&g_pl1y[idx]);
        float vc = __ldcg(&g_pcnt[idx]);
        #pragma unroll
        for (int o = 16; o > 0; o >>= 1) {
            vb += __shfl_down_sync(0xFFFFFFFFu, vb, o);
            vx += __shfl_down_sync(0xFFFFFFFFu, vx, o);
            vy += __shfl_down_sync(0xFFFFFFFFu, vy, o);
            vc += __shfl_down_sync(0xFFFFFFFFu, vc, o);
        }
        if (lane == 0)
            acc += 2.0f * vb * (1.0f / (float)HWc) + (vx + vy) / vc;
    }

    __shared__ float sacc[8];
    if (lane == 0) sacc[warp] = acc;
    __syncthreads();
    if (threadIdx.x == 0) {
        float sum = 0.0f;
        #pragma unroll
        for (int i = 0; i < 8; i++) sum += sacc[i];
        out[0] = sum / (float)PAIRS;
    }
}

extern "C" void kernel_launch(void* const* d_in, const int* in_sizes, int n_in,
                              void* d_out, int out_size)
{
    const float* fm  = (const float*)d_in[0];   // feature_maps (4,57,512,512) f32
    const float* lms = (const float*)d_in[1];   // landmarks (4,19,2) f32
    float* out = (float*)d_out;

    hm_main_kernel<<<NBLOCKS, THREADS>>>(fm, lms, out);
}

// round 5
// speedup vs baseline: 1.2250x; 1.1875x over previous
#include <cuda_runtime.h>

// Problem constants (fixed shapes from reference)
#define BB 4
#define NN 19
#define HH 512
#define WW 512
#define HWc (HH * WW)          // 262144
#define CC 57
#define PAIRS (BB * NN)        // 76
#define TILES 32
#define NBLOCKS (PAIRS * TILES)             // 2432 worker CTAs (+1 watcher)
#define THREADS 256
#define V_PER_TILE (HWc / 4 / TILES)        // 2048 float4 per tile
#define V_PER_THREAD (V_PER_TILE / THREADS) // 8 float4 per thread per plane

// Per-pair accumulators. Zero at module load; the watcher resets them to zero
// after consuming -> state identical on every graph replay.
__device__ float g_bce[PAIRS];
__device__ float g_l1x[PAIRS];
__device__ float g_l1y[PAIRS];
__device__ float g_cnt[PAIRS];
__device__ unsigned int g_count = 0;

__global__ __launch_bounds__(THREADS, 6) void hm_main_kernel(
    const float* __restrict__ fm, const float* __restrict__ lms,
    float* __restrict__ out)
{
    // ---------------- watcher CTA: finalize ----------------
    if (blockIdx.x == NBLOCKS) {
        const int tid = threadIdx.x;
        if (tid == 0) {
            volatile unsigned int* vc = &g_count;
            while (*vc != (unsigned int)NBLOCKS) __nanosleep(200);
        }
        __syncthreads();
        __threadfence();   // acquire: accumulator REDs visible after count

        float t = 0.0f;
        if (tid < PAIRS) {
            const float vb = __ldcg(&g_bce[tid]);
            const float vx = __ldcg(&g_l1x[tid]);
            const float vy = __ldcg(&g_l1y[tid]);
            const float vn = __ldcg(&g_cnt[tid]);
            t = 2.0f * vb * (1.0f / (float)HWc) + (vx + vy) / vn;
        }
        #pragma unroll
        for (int o = 16; o > 0; o >>= 1)
            t += __shfl_down_sync(0xFFFFFFFFu, t, o);

        __shared__ float s[8];
        const int warp = tid >> 5, lane = tid & 31;
        if (lane == 0) s[warp] = t;
        __syncthreads();
        if (tid == 0) {
            float sum = 0.0f;
            #pragma unroll
            for (int i = 0; i < 8; i++) sum += s[i];
            out[0] = sum / (float)PAIRS;
        }
        // reset state for the next graph replay (end state == initial state)
        if (tid < PAIRS) {
            g_bce[tid] = 0.0f; g_l1x[tid] = 0.0f;
            g_l1y[tid] = 0.0f; g_cnt[tid] = 0.0f;
        }
        if (tid == 0) g_count = 0;
        return;
    }

    // ---------------- worker CTAs ----------------
    const int pair = blockIdx.x / TILES;
    const int tile = blockIdx.x % TILES;
    const int b = pair / NN;
    const int n = pair % NN;

    // landmark -> integer center (matches (lm * [H,W]).astype(int32) truncation)
    const float lx = lms[pair * 2 + 0];
    const float ly = lms[pair * 2 + 1];
    const int x = (int)(lx * (float)HH);
    const int y = (int)(ly * (float)WW);

    const size_t base = ((size_t)(b * CC + n)) * (size_t)HWc;
    const float4* __restrict__ pL = (const float4*)(fm + base);
    const float4* __restrict__ pX = (const float4*)(fm + base + (size_t)NN * HWc);
    const float4* __restrict__ pY = (const float4*)(fm + base + (size_t)(2 * NN) * HWc);

    float bce = 0.0f, l1x = 0.0f, l1y = 0.0f;
    int cnt = 0;

    const int vbase = tile * V_PER_TILE + threadIdx.x;

    #pragma unroll
    for (int k = 0; k < V_PER_THREAD; k++) {
        const int v = vbase + k * THREADS;
        const float4 L  = __ldcs(pL + v);   // evict-streaming: 239MB, no reuse
        const float4 PX = __ldcs(pX + v);
        const float4 PY = __ldcs(pY + v);

        const int h = v >> 7;           // v / 128 (128 float4 per row)
        const int w = (v & 127) << 2;   // starting column of this float4

        const int di = h - x;           // row delta (constant across the 4 lanes)
        const int di2 = di * di;
        const float offx = -(float)di * (1.0f / 40.0f);

        float Lv[4]  = {L.x, L.y, L.z, L.w};
        float PXv[4] = {PX.x, PX.y, PX.z, PX.w};
        float PYv[4] = {PY.x, PY.y, PY.z, PY.w};

        #pragma unroll
        for (int j = 0; j < 4; j++) {
            const int dj = (w + j) - y;
            const bool heat = (di2 + dj * dj) <= 1600;   // == (sqrt(d2) <= 40)
            const float l = Lv[j];
            // softplus(-|l|) via fast MUFU log/exp (rel_err budget 1e-3; this is ~1e-6)
            const float sp = __logf(1.0f + __expf(-fabsf(l)));
            bce += fmaxf(l, 0.0f) + sp - (heat ? l : 0.0f);
            if (heat) {
                const float offy = -(float)dj * (1.0f / 40.0f);
                l1x += fabsf(PXv[j] - offx);
                l1y += fabsf(PYv[j] - offy);
                cnt++;
            }
        }
    }

    // block reduction: warp shfl, then cross-warp via smem
    float c = (float)cnt;
    #pragma unroll
    for (int o = 16; o > 0; o >>= 1) {
        bce += __shfl_down_sync(0xFFFFFFFFu, bce, o);
        l1x += __shfl_down_sync(0xFFFFFFFFu, l1x, o);
        l1y += __shfl_down_sync(0xFFFFFFFFu, l1y, o);
        c   += __shfl_down_sync(0xFFFFFFFFu, c, o);
    }

    __shared__ float s0[8], s1[8], s2[8], s3[8];
    const int warp = threadIdx.x >> 5;
    const int lane = threadIdx.x & 31;
    if (lane == 0) { s0[warp] = bce; s1[warp] = l1x; s2[warp] = l1y; s3[warp] = c; }
    __syncthreads();
    // warps 1..7 retire here; only thread0 pays the fence.

    if (threadIdx.x == 0) {
        float v0 = 0.f, v1 = 0.f, v2 = 0.f, v3 = 0.f;
        #pragma unroll
        for (int i = 0; i < 8; i++) {
            v0 += s0[i]; v1 += s1[i]; v2 += s2[i]; v3 += s3[i];
        }
        // fire-and-forget REDG accumulation (results unused -> no round trip)
        atomicAdd(&g_bce[pair], v0);
        atomicAdd(&g_l1x[pair], v1);
        atomicAdd(&g_l1y[pair], v2);
        atomicAdd(&g_cnt[pair], v3);
        __threadfence();              // order data REDs before the count RED
        atomicAdd(&g_count, 1u);      // fire-and-forget
    }
}

extern "C" void kernel_launch(void* const* d_in, const int* in_sizes, int n_in,
                              void* d_out, int out_size)
{
    const float* fm  = (const float*)d_in[0];   // feature_maps (4,57,512,512) f32
    const float* lms = (const float*)d_in[1];   // landmarks (4,19,2) f32
    float* out = (float*)d_out;

    hm_main_kernel<<<NBLOCKS + 1, THREADS>>>(fm, lms, out);
}

// round 6
// speedup vs baseline: 2.3432x; 1.9128x over previous
#include <cuda_runtime.h>

// Problem constants (fixed shapes from reference)
#define BB 4
#define NN 19
#define HH 512
#define WW 512
#define HWc (HH * WW)          // 262144
#define CC 57
#define PAIRS (BB * NN)        // 76
#define TILES 32
#define NBLOCKS (PAIRS * TILES)             // 2432 worker CTAs (+1 watcher)
#define THREADS 256
#define V_PER_TILE (HWc / 4 / TILES)        // 2048 float4 per tile
#define V_PER_THREAD (V_PER_TILE / THREADS) // 8 float4 per thread per plane

// Per-pair accumulators. Zero at module load; the watcher resets them to zero
// after consuming -> state identical on every graph replay.
__device__ float g_bce[PAIRS];
__device__ float g_l1x[PAIRS];
__device__ float g_l1y[PAIRS];
__device__ float g_cnt[PAIRS];
__device__ unsigned int g_count = 0;

__global__ __launch_bounds__(THREADS, 6) void hm_main_kernel(
    const float* __restrict__ fm, const float* __restrict__ lms,
    float* __restrict__ out)
{
    // ---------------- watcher CTA: finalize ----------------
    if (blockIdx.x == NBLOCKS) {
        const int tid = threadIdx.x;
        if (tid == 0) {
            volatile unsigned int* vc = &g_count;
            while (*vc != (unsigned int)NBLOCKS) __nanosleep(200);
        }
        __syncthreads();
        __threadfence();   // acquire: accumulator REDs visible after count

        float t = 0.0f;
        if (tid < PAIRS) {
            const float vb = __ldcg(&g_bce[tid]);
            const float vx = __ldcg(&g_l1x[tid]);
            const float vy = __ldcg(&g_l1y[tid]);
            const float vn = __ldcg(&g_cnt[tid]);
            t = 2.0f * vb * (1.0f / (float)HWc) + (vx + vy) / vn;
        }
        #pragma unroll
        for (int o = 16; o > 0; o >>= 1)
            t += __shfl_down_sync(0xFFFFFFFFu, t, o);

        __shared__ float s[8];
        const int warp = tid >> 5, lane = tid & 31;
        if (lane == 0) s[warp] = t;
        __syncthreads();
        if (tid == 0) {
            float sum = 0.0f;
            #pragma unroll
            for (int i = 0; i < 8; i++) sum += s[i];
            out[0] = sum / (float)PAIRS;
        }
        // reset state for the next graph replay (end state == initial state)
        if (tid < PAIRS) {
            g_bce[tid] = 0.0f; g_l1x[tid] = 0.0f;
            g_l1y[tid] = 0.0f; g_cnt[tid] = 0.0f;
        }
        if (tid == 0) g_count = 0;
        return;
    }

    // ---------------- worker CTAs ----------------
    const int pair = blockIdx.x / TILES;
    const int tile = blockIdx.x % TILES;
    const int b = pair / NN;
    const int n = pair % NN;

    // landmark -> integer center (matches (lm * [H,W]).astype(int32) truncation)
    const float lx = lms[pair * 2 + 0];
    const float ly = lms[pair * 2 + 1];
    const int x = (int)(lx * (float)HH);
    const int y = (int)(ly * (float)WW);

    const size_t base = ((size_t)(b * CC + n)) * (size_t)HWc;
    const float4* __restrict__ pL = (const float4*)(fm + base);
    const float4* __restrict__ pX = (const float4*)(fm + base + (size_t)NN * HWc);
    const float4* __restrict__ pY = (const float4*)(fm + base + (size_t)(2 * NN) * HWc);

    float bce = 0.0f, l1x = 0.0f, l1y = 0.0f;
    int cnt = 0;

    const int vbase = tile * V_PER_TILE + threadIdx.x;

    #pragma unroll
    for (int k = 0; k < V_PER_THREAD; k++) {
        const int v = vbase + k * THREADS;
        const float4 L = __ldcs(pL + v);    // logits: always needed (79.6MB stream)

        const int h = v >> 7;           // v / 128 (128 float4 per row)
        const int w = (v & 127) << 2;   // starting column of this float4

        const int di = h - x;
        const int di2 = di * di;
        const int rem = 1600 - di2;     // dj^2 budget for this row

        float Lv[4] = {L.x, L.y, L.z, L.w};

        // bce hot terms (no heat dependence): max(l,0) + softplus(-|l|)
        #pragma unroll
        for (int j = 0; j < 4; j++) {
            const float l = Lv[j];
            bce += fmaxf(l, 0.0f) + __logf(1.0f + __expf(-fabsf(l)));
        }

        // Can any of the 4 lanes be inside the disk? (exact test)
        const int dj0 = w - y;               // lane j has dj = dj0 + j
        const int djc = (dj0 > 0) ? dj0 : ((dj0 + 3 < 0) ? -(dj0 + 3) : 0);
        const bool need = (rem >= 0) && (djc * djc <= rem);

        if (need) {
            // PX/PY loaded only inside (or at the fringe of) the disk: ~2% of px
            const float4 PX = __ldcs(pX + v);
            const float4 PY = __ldcs(pY + v);
            const float offx = -(float)di * (1.0f / 40.0f);
            float PXv[4] = {PX.x, PX.y, PX.z, PX.w};
            float PYv[4] = {PY.x, PY.y, PY.z, PY.w};
            #pragma unroll
            for (int j = 0; j < 4; j++) {
                const int dj = dj0 + j;
                if (dj * dj <= rem) {        // heat == 1
                    bce -= Lv[j];
                    const float offy = -(float)dj * (1.0f / 40.0f);
                    l1x += fabsf(PXv[j] - offx);
                    l1y += fabsf(PYv[j] - offy);
                    cnt++;
                }
            }
        }
    }

    // block reduction: warp shfl, then cross-warp via smem
    float c = (float)cnt;
    #pragma unroll
    for (int o = 16; o > 0; o >>= 1) {
        bce += __shfl_down_sync(0xFFFFFFFFu, bce, o);
        l1x += __shfl_down_sync(0xFFFFFFFFu, l1x, o);
        l1y += __shfl_down_sync(0xFFFFFFFFu, l1y, o);
        c   += __shfl_down_sync(0xFFFFFFFFu, c, o);
    }

    __shared__ float s0[8], s1[8], s2[8], s3[8];
    const int warp = threadIdx.x >> 5;
    const int lane = threadIdx.x & 31;
    if (lane == 0) { s0[warp] = bce; s1[warp] = l1x; s2[warp] = l1y; s3[warp] = c; }
    __syncthreads();
    // warps 1..7 retire here; only thread0 pays the fence.

    if (threadIdx.x == 0) {
        float v0 = 0.f, v1 = 0.f, v2 = 0.f, v3 = 0.f;
        #pragma unroll
        for (int i = 0; i < 8; i++) {
            v0 += s0[i]; v1 += s1[i]; v2 += s2[i]; v3 += s3[i];
        }
        // fire-and-forget REDG accumulation (results unused -> no round trip)
        atomicAdd(&g_bce[pair], v0);
        atomicAdd(&g_l1x[pair], v1);
        atomicAdd(&g_l1y[pair], v2);
        atomicAdd(&g_cnt[pair], v3);
        __threadfence();              // order data REDs before the count RED
        atomicAdd(&g_count, 1u);      // fire-and-forget
    }
}

extern "C" void kernel_launch(void* const* d_in, const int* in_sizes, int n_in,
                              void* d_out, int out_size)
{
    const float* fm  = (const float*)d_in[0];   // feature_maps (4,57,512,512) f32
    const float* lms = (const float*)d_in[1];   // landmarks (4,19,2) f32
    float* out = (float*)d_out;

    hm_main_kernel<<<NBLOCKS + 1, THREADS>>>(fm, lms, out);
}